// round 12
// baseline (speedup 1.0000x reference)
#include <cuda_runtime.h>
#include <cuda_bf16.h>
#include <cuda_fp16.h>
#include <math.h>
#include <stdint.h>

#define N_ELEM 131072
#define C_DIM  512
#define G_DIM  4096
#define NOUT   1024     // Wf cols || Wg cols

// ---------------- scratch (device globals; no allocation allowed) ----------------
__device__ __nv_bfloat16 g_xhi[(size_t)N_ELEM * C_DIM];   // 128 MB
__device__ __nv_bfloat16 g_xlo[(size_t)N_ELEM * C_DIM];   // 128 MB
__device__ __nv_bfloat16 g_whi[(size_t)NOUT * C_DIM];     // 1 MB, K-major [n][k]
__device__ __nv_bfloat16 g_wlo[(size_t)NOUT * C_DIM];     // 1 MB
__device__ __half g_eg[(size_t)N_ELEM * C_DIM];           // 128 MB (fp16)
__device__ float g_denom[G_DIM * C_DIM];                  // 8 MB (then reciprocal)
__device__ float g_y[G_DIM * C_DIM];                      // 8 MB
__device__ float g_yh[G_DIM * C_DIM];                     // 8 MB

#define MMA16816(d, a0, a1, a2, a3, b0, b1) \
    asm volatile("mma.sync.aligned.m16n8k16.row.col.f32.bf16.bf16.f32 " \
                 "{%0,%1,%2,%3}, {%4,%5,%6,%7}, {%8,%9}, {%0,%1,%2,%3};" \
                 : "+f"((d)[0]), "+f"((d)[1]), "+f"((d)[2]), "+f"((d)[3]) \
                 : "r"(a0), "r"(a1), "r"(a2), "r"(a3), "r"(b0), "r"(b1))

__device__ __forceinline__ uint32_t smem_u32(const void* p) {
    uint32_t a;
    asm("{ .reg .u64 t; cvta.to.shared.u64 t, %1; cvt.u32.u64 %0, t; }" : "=r"(a) : "l"(p));
    return a;
}
__device__ __forceinline__ void cp16(uint32_t saddr, const void* g) {
    asm volatile("cp.async.cg.shared.global [%0], [%1], 16;" :: "r"(saddr), "l"(g));
}

// ---------------- zero accumulators ----------------
__global__ void zero_kernel() {
    int i = blockIdx.x * blockDim.x + threadIdx.x;   // G*C/4
    float4 z = make_float4(0.f, 0.f, 0.f, 0.f);
    ((float4*)g_denom)[i] = z;
    ((float4*)g_y)[i] = z;
}

// ---------------- denom -> 1/denom (between the two gemm halves) ----------------
__global__ void rcp_kernel() {
    int i = blockIdx.x * blockDim.x + threadIdx.x;   // G*C/4
    float4 d = ((float4*)g_denom)[i];
    d.x = 1.0f / d.x;
    d.y = 1.0f / d.y;
    d.z = 1.0f / d.z;
    d.w = 1.0f / d.w;
    ((float4*)g_denom)[i] = d;
}

// ---------------- split x into bf16 hi/lo (verified in R5) ----------------
__global__ void convert_x_kernel(const float* __restrict__ x) {
    size_t idx = (size_t)blockIdx.x * blockDim.x + threadIdx.x;  // N*C/4
    float4 v = ((const float4*)x)[idx];
    __nv_bfloat16 h0 = __float2bfloat16(v.x);
    __nv_bfloat16 h1 = __float2bfloat16(v.y);
    __nv_bfloat16 h2 = __float2bfloat16(v.z);
    __nv_bfloat16 h3 = __float2bfloat16(v.w);
    __nv_bfloat162 ha; ha.x = h0; ha.y = h1;
    __nv_bfloat162 hb; hb.x = h2; hb.y = h3;
    ((__nv_bfloat162*)g_xhi)[2 * idx]     = ha;
    ((__nv_bfloat162*)g_xhi)[2 * idx + 1] = hb;
    __nv_bfloat162 la, lb;
    la.x = __float2bfloat16(v.x - __bfloat162float(h0));
    la.y = __float2bfloat16(v.y - __bfloat162float(h1));
    lb.x = __float2bfloat16(v.z - __bfloat162float(h2));
    lb.y = __float2bfloat16(v.w - __bfloat162float(h3));
    ((__nv_bfloat162*)g_xlo)[2 * idx]     = la;
    ((__nv_bfloat162*)g_xlo)[2 * idx + 1] = lb;
}

// ---------------- build Whi/Wlo [n=1024][k=512] K-major bf16 ----------------
__global__ void build_w_kernel(const float* __restrict__ Wf,
                               const float* __restrict__ Wg) {
    int i = blockIdx.x * blockDim.x + threadIdx.x;   // NOUT*C_DIM
    int n = i >> 9;
    int k = i & 511;
    const float* W = (n < 512) ? Wf : Wg;
    float w = W[(size_t)k * C_DIM + (n & 511)];
    __nv_bfloat16 hi = __float2bfloat16(w);
    g_whi[i] = hi;
    g_wlo[i] = __float2bfloat16(w - __bfloat162float(hi));
}

// ---------------- mma.sync bf16-split GEMM halves ------------------------------
// A now precomputed bf16 hi/lo in gmem -> pure cp.async staging (no LDG/cvt/STS
// on the critical path; conversion redundancy removed). Fragment/MMA body and
// epilogues byte-identical to R11 (1405us best).
// IS_G=true : eg = __expf(x Wg + bg) -> fp16 store; denom += quantized eg.
// IS_G=false: fx in regs -> w = eg_fp16 * rcp_denom, atomicAdd y += fx*w.
#define SPITCH 40
#define PITCHB 80
#define TILE_E (128 * SPITCH)        // bf16 elems per tile
#define TILE_B (TILE_E * 2)          // 10240 bytes per tile
#define STG_E  (4 * TILE_E)          // elems per stage (AHI, ALO, BHI, BLO)
#define STG_B  (4 * TILE_B)          // 40960 bytes per stage

template <bool IS_G>
__global__ __launch_bounds__(256, 2)
void gemm_half(const int* __restrict__ ix, const float* __restrict__ bias) {
    extern __shared__ __nv_bfloat16 sm[];

    const int tid  = threadIdx.x;
    const int l    = tid & 31;
    const int warp = tid >> 5;
    const int bx   = blockIdx.x;          // 0..3 -> 128-col stripe of this half
    const int row0 = blockIdx.y * 128;
    const int n0g  = (IS_G ? 512 : 0) + bx * 128;

    const int wm = warp >> 2;             // 0..1
    const int wn = warp & 3;              // 0..3
    const int m_base = wm * 64;
    const int n_base = wn * 32;
    const int gid = l >> 2, tig = l & 3;

    const uint32_t sbase = smem_u32(sm);

    float acc[4][4][4];
#pragma unroll
    for (int t = 0; t < 4; t++)
#pragma unroll
        for (int n = 0; n < 4; n++)
#pragma unroll
            for (int r = 0; r < 4; r++) acc[t][n][r] = 0.f;

#define LOAD_STAGE(BUF, CH) do {                                              \
        const int kc_ = (CH) * 32;                                            \
        const uint32_t st_ = sbase + (BUF) * STG_B;                           \
        _Pragma("unroll")                                                     \
        for (int i_ = 0; i_ < 2; i_++) {                                      \
            int u_ = tid + i_ * 256;                                          \
            int r_ = u_ >> 2, sg_ = u_ & 3;                                   \
            uint32_t so_ = r_ * PITCHB + sg_ * 16;                            \
            size_t ga_ = (size_t)(row0 + r_) * C_DIM + kc_ + sg_ * 8;         \
            size_t gb_ = (size_t)(n0g + r_) * C_DIM + kc_ + sg_ * 8;          \
            cp16(st_ + so_,              g_xhi + ga_);                        \
            cp16(st_ + TILE_B + so_,     g_xlo + ga_);                        \
            cp16(st_ + 2 * TILE_B + so_, g_whi + gb_);                        \
            cp16(st_ + 3 * TILE_B + so_, g_wlo + gb_);                        \
        }                                                                     \
        asm volatile("cp.async.commit_group;" ::: "memory");                  \
    } while (0)

    LOAD_STAGE(0, 0);
    asm volatile("cp.async.wait_group 0;" ::: "memory");
    __syncthreads();

    for (int it = 0; it < 16; it++) {
        const int cur = it & 1;
        if (it + 1 < 16) LOAD_STAGE(cur ^ 1, it + 1);

        const __nv_bfloat16* Ahi = sm + cur * STG_E;
        const __nv_bfloat16* Alo = Ahi + TILE_E;
        const __nv_bfloat16* Bhi = Ahi + 2 * TILE_E;
        const __nv_bfloat16* Blo = Ahi + 3 * TILE_E;

#pragma unroll
        for (int s = 0; s < 2; s++) {
            const int k0 = s * 16 + 2 * tig;
            uint32_t bH[4][2], bL[4][2];
#pragma unroll
            for (int nt = 0; nt < 4; nt++) {
                const int rn = n_base + nt * 8 + gid;
                bH[nt][0] = *(const uint32_t*)(Bhi + rn * SPITCH + k0);
                bH[nt][1] = *(const uint32_t*)(Bhi + rn * SPITCH + k0 + 8);
                bL[nt][0] = *(const uint32_t*)(Blo + rn * SPITCH + k0);
                bL[nt][1] = *(const uint32_t*)(Blo + rn * SPITCH + k0 + 8);
            }
#pragma unroll
            for (int t = 0; t < 4; t++) {
                const int r = m_base + t * 16 + gid;
                uint32_t aH[4], aL[4];
                aH[0] = *(const uint32_t*)(Ahi + r * SPITCH + k0);
                aH[1] = *(const uint32_t*)(Ahi + (r + 8) * SPITCH + k0);
                aH[2] = *(const uint32_t*)(Ahi + r * SPITCH + k0 + 8);
                aH[3] = *(const uint32_t*)(Ahi + (r + 8) * SPITCH + k0 + 8);
                aL[0] = *(const uint32_t*)(Alo + r * SPITCH + k0);
                aL[1] = *(const uint32_t*)(Alo + (r + 8) * SPITCH + k0);
                aL[2] = *(const uint32_t*)(Alo + r * SPITCH + k0 + 8);
                aL[3] = *(const uint32_t*)(Alo + (r + 8) * SPITCH + k0 + 8);
                // pass-major: acc[t][nt] reuse distance = 4 independent MMAs
#pragma unroll
                for (int nt = 0; nt < 4; nt++)
                    MMA16816(acc[t][nt], aH[0], aH[1], aH[2], aH[3],
                             bH[nt][0], bH[nt][1]);
#pragma unroll
                for (int nt = 0; nt < 4; nt++)
                    MMA16816(acc[t][nt], aH[0], aH[1], aH[2], aH[3],
                             bL[nt][0], bL[nt][1]);
#pragma unroll
                for (int nt = 0; nt < 4; nt++)
                    MMA16816(acc[t][nt], aL[0], aL[1], aL[2], aL[3],
                             bH[nt][0], bH[nt][1]);
            }
        }

        if (it + 1 < 16) asm volatile("cp.async.wait_group 0;" ::: "memory");
        __syncthreads();
    }
#undef LOAD_STAGE

    // ---- epilogue (identical to R11) ----
#pragma unroll
    for (int t = 0; t < 4; t++) {
#pragma unroll
        for (int h = 0; h < 2; h++) {
            const int m = row0 + m_base + t * 16 + gid + h * 8;
            const int grp = ix[m];
#pragma unroll
            for (int nt = 0; nt < 4; nt++) {
                const int cg = n0g + n_base + nt * 8 + 2 * tig;
                const int cw = cg & 511;
                float v0 = acc[t][nt][2 * h]     + bias[cw];
                float v1 = acc[t][nt][2 * h + 1] + bias[cw + 1];
                if (IS_G) {
                    v0 = __expf(v0);
                    v1 = __expf(v1);
                    __half2 eq = __floats2half2_rn(v0, v1);
                    *(__half2*)&g_eg[(size_t)m * C_DIM + cw] = eq;
                    float q0 = __half2float(__low2half(eq));
                    float q1 = __half2float(__high2half(eq));
                    float* dp = &g_denom[(size_t)grp * C_DIM + cw];
                    atomicAdd(dp,     q0);
                    atomicAdd(dp + 1, q1);
                } else {
                    __half2 eh = *(const __half2*)&g_eg[(size_t)m * C_DIM + cw];
                    float2 e = __half22float2(eh);
                    float2 d = *(const float2*)&g_denom[(size_t)grp * C_DIM + cw]; // reciprocal
                    float* yp = &g_y[(size_t)grp * C_DIM + cw];
                    atomicAdd(yp,     v0 * e.x * d.x);
                    atomicAdd(yp + 1, v1 * e.y * d.y);
                }
            }
        }
    }
}

// ---------------- yh = y @ Wh + bh (fp32 SIMT, small) ----------------
__global__ __launch_bounds__(256, 2)
void gemm_h_kernel(const float* __restrict__ Wh, const float* __restrict__ bh)
{
    constexpr int BM = 128, BN = 128, BK = 16;
    __shared__ float As[BK][BM];
    __shared__ float Bs[BK][BN];

    const int tid  = threadIdx.x;
    const int col0 = blockIdx.x * BN;
    const int row0 = blockIdx.y * BM;
    const int ty = tid >> 4, tx = tid & 15;
    const int trow = ty * 8, tcol = tx * 8;

    float acc[8][8];
#pragma unroll
    for (int i = 0; i < 8; i++)
#pragma unroll
        for (int j = 0; j < 8; j++) acc[i][j] = 0.f;

    for (int k0 = 0; k0 < C_DIM; k0 += BK) {
#pragma unroll
        for (int s = 0; s < 2; s++) {
            int ll = tid + s * 256;
            int ar  = ll >> 2;
            int akq = (ll & 3) * 4;
            float4 av = *(const float4*)&g_y[(size_t)(row0 + ar) * C_DIM + k0 + akq];
            As[akq + 0][ar] = av.x;
            As[akq + 1][ar] = av.y;
            As[akq + 2][ar] = av.z;
            As[akq + 3][ar] = av.w;
            int bk  = ll >> 5;
            int bcq = (ll & 31) * 4;
            float4 bv = *(const float4*)&Wh[(size_t)(k0 + bk) * C_DIM + col0 + bcq];
            *(float4*)&Bs[bk][bcq] = bv;
        }
        __syncthreads();
#pragma unroll
        for (int k = 0; k < BK; k++) {
            float a[8], b[8];
#pragma unroll
            for (int i = 0; i < 8; i++) a[i] = As[k][trow + i];
#pragma unroll
            for (int j = 0; j < 8; j++) b[j] = Bs[k][tcol + j];
#pragma unroll
            for (int i = 0; i < 8; i++)
#pragma unroll
                for (int j = 0; j < 8; j++)
                    acc[i][j] = fmaf(a[i], b[j], acc[i][j]);
        }
        __syncthreads();
    }

    float bv[8];
#pragma unroll
    for (int j = 0; j < 8; j++) bv[j] = bh[col0 + tcol + j];
#pragma unroll
    for (int i = 0; i < 8; i++) {
        size_t off = (size_t)(row0 + trow + i) * C_DIM + col0 + tcol;
        *(float4*)&g_yh[off]     = make_float4(acc[i][0] + bv[0], acc[i][1] + bv[1],
                                               acc[i][2] + bv[2], acc[i][3] + bv[3]);
        *(float4*)&g_yh[off + 4] = make_float4(acc[i][4] + bv[4], acc[i][5] + bv[5],
                                               acc[i][6] + bv[6], acc[i][7] + bv[7]);
    }
}

// ---------------- out[n] = yh[ix[n]] ----------------
__global__ void gather_kernel(const int* __restrict__ ix, float* __restrict__ out) {
    size_t idx = (size_t)blockIdx.x * blockDim.x + threadIdx.x;  // N*C/4
    int n  = (int)(idx >> 7);
    int cq = (int)(idx & 127) << 2;
    int g  = ix[n];
    *(float4*)&out[((size_t)n << 9) + cq] = *(const float4*)&g_yh[((size_t)g << 9) + cq];
}

extern "C" void kernel_launch(void* const* d_in, const int* in_sizes, int n_in,
                              void* d_out, int out_size) {
    const float* x  = (const float*)d_in[0];
    const int*   ix = (const int*)d_in[1];
    const float* Wf = (const float*)d_in[2];
    const float* bf = (const float*)d_in[3];
    const float* Wg = (const float*)d_in[4];
    const float* bg = (const float*)d_in[5];
    const float* Wh = (const float*)d_in[6];
    const float* bh = (const float*)d_in[7];
    float* out = (float*)d_out;

    const int SMEM = 2 * STG_B;   // 81920 bytes
    cudaFuncSetAttribute(gemm_half<true>,  cudaFuncAttributeMaxDynamicSharedMemorySize, SMEM);
    cudaFuncSetAttribute(gemm_half<false>, cudaFuncAttributeMaxDynamicSharedMemorySize, SMEM);

    zero_kernel<<<(G_DIM * C_DIM / 4) / 256, 256>>>();
    convert_x_kernel<<<(N_ELEM * (C_DIM / 4)) / 256, 256>>>(x);
    build_w_kernel<<<(NOUT * C_DIM) / 256, 256>>>(Wf, Wg);

    dim3 g1(4, N_ELEM / 128);
    gemm_half<true><<<g1, 256, SMEM>>>(ix, bg);       // eg(fp16) + denom
    rcp_kernel<<<(G_DIM * C_DIM / 4) / 256, 256>>>(); // denom -> 1/denom
    gemm_half<false><<<g1, 256, SMEM>>>(ix, bf);      // fx, fused aggregation

    dim3 g2(C_DIM / 128, G_DIM / 128);
    gemm_h_kernel<<<g2, 256>>>(Wh, bh);

    gather_kernel<<<(N_ELEM * (C_DIM / 4)) / 256, 256>>>(ix, out);
}

// round 13
// speedup vs baseline: 1.6666x; 1.6666x over previous
#include <cuda_runtime.h>
#include <cuda_bf16.h>
#include <cuda_fp16.h>
#include <math.h>
#include <stdint.h>

#define N_ELEM 131072
#define C_DIM  512
#define G_DIM  4096
#define NOUT   1024     // Wf cols || Wg cols

// ---------------- scratch (device globals; no allocation allowed) ----------------
__device__ __nv_bfloat16 g_whi[(size_t)NOUT * C_DIM];     // 1 MB, K-major [n][k]
__device__ __nv_bfloat16 g_wlo[(size_t)NOUT * C_DIM];     // 1 MB
__device__ __nv_bfloat16 g_whh[(size_t)C_DIM * C_DIM];    // 0.5 MB, Wh hi, K-major
__device__ __nv_bfloat16 g_wlh[(size_t)C_DIM * C_DIM];    // 0.5 MB, Wh lo
__device__ __half g_eg[(size_t)N_ELEM * C_DIM];           // 128 MB (fp16)
__device__ float g_denom[G_DIM * C_DIM];                  // 8 MB (then reciprocal)
__device__ float g_y[G_DIM * C_DIM];                      // 8 MB
__device__ float g_yh[G_DIM * C_DIM];                     // 8 MB

#define MMA16816(d, a0, a1, a2, a3, b0, b1) \
    asm volatile("mma.sync.aligned.m16n8k16.row.col.f32.bf16.bf16.f32 " \
                 "{%0,%1,%2,%3}, {%4,%5,%6,%7}, {%8,%9}, {%0,%1,%2,%3};" \
                 : "+f"((d)[0]), "+f"((d)[1]), "+f"((d)[2]), "+f"((d)[3]) \
                 : "r"(a0), "r"(a1), "r"(a2), "r"(a3), "r"(b0), "r"(b1))

__device__ __forceinline__ uint32_t smem_u32(const void* p) {
    uint32_t a;
    asm("{ .reg .u64 t; cvta.to.shared.u64 t, %1; cvt.u32.u64 %0, t; }" : "=r"(a) : "l"(p));
    return a;
}
__device__ __forceinline__ void cp16(uint32_t saddr, const void* g) {
    asm volatile("cp.async.cg.shared.global [%0], [%1], 16;" :: "r"(saddr), "l"(g));
}

// ---------------- zero accumulators ----------------
__global__ void zero_kernel() {
    int i = blockIdx.x * blockDim.x + threadIdx.x;   // G*C/4
    float4 z = make_float4(0.f, 0.f, 0.f, 0.f);
    ((float4*)g_denom)[i] = z;
    ((float4*)g_y)[i] = z;
}

// ---------------- denom -> 1/denom (between the two gemm halves) ----------------
__global__ void rcp_kernel() {
    int i = blockIdx.x * blockDim.x + threadIdx.x;   // G*C/4
    float4 d = ((float4*)g_denom)[i];
    d.x = 1.0f / d.x;
    d.y = 1.0f / d.y;
    d.z = 1.0f / d.z;
    d.w = 1.0f / d.w;
    ((float4*)g_denom)[i] = d;
}

// ---------------- build Whi/Wlo [n=1024][k=512] K-major bf16 ----------------
__global__ void build_w_kernel(const float* __restrict__ Wf,
                               const float* __restrict__ Wg) {
    int i = blockIdx.x * blockDim.x + threadIdx.x;   // NOUT*C_DIM
    int n = i >> 9;
    int k = i & 511;
    const float* W = (n < 512) ? Wf : Wg;
    float w = W[(size_t)k * C_DIM + (n & 511)];
    __nv_bfloat16 hi = __float2bfloat16(w);
    g_whi[i] = hi;
    g_wlo[i] = __float2bfloat16(w - __bfloat162float(hi));
}

// ---------------- build Wh hi/lo [n=512][k=512] K-major bf16 ----------------
__global__ void build_wh_kernel(const float* __restrict__ Wh) {
    int i = blockIdx.x * blockDim.x + threadIdx.x;   // C_DIM*C_DIM
    int n = i >> 9;
    int k = i & 511;
    float w = Wh[(size_t)k * C_DIM + n];
    __nv_bfloat16 hi = __float2bfloat16(w);
    g_whh[i] = hi;
    g_wlh[i] = __float2bfloat16(w - __bfloat162float(hi));
}

// ---------------- mma.sync bf16-split GEMM halves (R11 exact) -------------------
// A (x fp32) read once per k-chunk via LDG (L1-allocating; stripe-twin CTAs hit
// L1), split hi/lo in regs, STS; B via cp.async. 3 MMA passes per chunk.
// IS_G=true : eg = __expf(x Wg + bg) -> fp16 store; denom += quantized eg.
// IS_G=false: fx in regs -> w = eg_fp16 * rcp_denom, atomicAdd y += fx*w.
#define SPITCH 40
#define TILE_E (128 * SPITCH)        // bf16 elems per tile (10240 B)
#define STG_E  (4 * TILE_E)          // elems per stage (4 tiles)

#define LOAD_A_IMPL(SRC, CH) do {                                             \
        const int kc_ = (CH) * 32;                                            \
        _Pragma("unroll")                                                     \
        for (int i_ = 0; i_ < 4; i_++) {                                      \
            int u_ = tid + i_ * 256;                                          \
            int r_ = u_ >> 3, s_ = u_ & 7;                                    \
            stg[i_] = *(const float4*)((SRC) + (size_t)(row0 + r_) * C_DIM + kc_ + s_ * 4); \
        }                                                                     \
    } while (0)

#define STORE_A_IMPL(BUF) do {                                                \
        __nv_bfloat16* ahi_ = sm + (BUF) * STG_E;                             \
        __nv_bfloat16* alo_ = ahi_ + TILE_E;                                  \
        _Pragma("unroll")                                                     \
        for (int i_ = 0; i_ < 4; i_++) {                                      \
            int u_ = tid + i_ * 256;                                          \
            int r_ = u_ >> 3, s_ = u_ & 7;                                    \
            float4 v_ = stg[i_];                                              \
            __nv_bfloat162 h01_, h23_, l01_, l23_;                            \
            h01_.x = __float2bfloat16(v_.x); h01_.y = __float2bfloat16(v_.y); \
            h23_.x = __float2bfloat16(v_.z); h23_.y = __float2bfloat16(v_.w); \
            l01_.x = __float2bfloat16(v_.x - __bfloat162float(h01_.x));       \
            l01_.y = __float2bfloat16(v_.y - __bfloat162float(h01_.y));       \
            l23_.x = __float2bfloat16(v_.z - __bfloat162float(h23_.x));       \
            l23_.y = __float2bfloat16(v_.w - __bfloat162float(h23_.y));       \
            uint2 H_, L_;                                                     \
            H_.x = *(uint32_t*)&h01_; H_.y = *(uint32_t*)&h23_;               \
            L_.x = *(uint32_t*)&l01_; L_.y = *(uint32_t*)&l23_;               \
            *(uint2*)(ahi_ + r_ * SPITCH + s_ * 4) = H_;                      \
            *(uint2*)(alo_ + r_ * SPITCH + s_ * 4) = L_;                      \
        }                                                                     \
    } while (0)

#define LOAD_B_IMPL(WH, WL, KSTRIDE, BUF, CH) do {                            \
        const int kc_ = (CH) * 32;                                            \
        uint32_t bhi_ = smem_u32(sm + (BUF) * STG_E + 2 * TILE_E);            \
        uint32_t blo_ = bhi_ + TILE_E * 2;                                    \
        _Pragma("unroll")                                                     \
        for (int i_ = 0; i_ < 2; i_++) {                                      \
            int u_ = tid + i_ * 256;                                          \
            int nr_ = u_ >> 2, ch_ = u_ & 3;                                  \
            size_t go_ = (size_t)(n0g + nr_) * (KSTRIDE) + kc_ + ch_ * 8;     \
            uint32_t so_ = nr_ * (SPITCH * 2) + ch_ * 16;                     \
            cp16(bhi_ + so_, (WH) + go_);                                     \
            cp16(blo_ + so_, (WL) + go_);                                     \
        }                                                                     \
        asm volatile("cp.async.commit_group;" ::: "memory");                  \
    } while (0)

#define MAINLOOP_BODY(ASRC, WH, WL, KSTRIDE)                                  \
    LOAD_B_IMPL(WH, WL, KSTRIDE, 0, 0);                                       \
    LOAD_A_IMPL(ASRC, 0);                                                     \
    STORE_A_IMPL(0);                                                          \
    asm volatile("cp.async.wait_group 0;" ::: "memory");                      \
    __syncthreads();                                                          \
    for (int it = 0; it < 16; it++) {                                         \
        const int cur = it & 1;                                               \
        if (it + 1 < 16) {                                                    \
            LOAD_B_IMPL(WH, WL, KSTRIDE, cur ^ 1, it + 1);                    \
            LOAD_A_IMPL(ASRC, it + 1);                                        \
        }                                                                     \
        const __nv_bfloat16* Ahi = sm + cur * STG_E;                          \
        const __nv_bfloat16* Alo = Ahi + TILE_E;                              \
        const __nv_bfloat16* Bhi = Ahi + 2 * TILE_E;                          \
        const __nv_bfloat16* Blo = Ahi + 3 * TILE_E;                          \
        _Pragma("unroll")                                                     \
        for (int s = 0; s < 2; s++) {                                         \
            const int k0 = s * 16 + 2 * tig;                                  \
            uint32_t bH[4][2], bL[4][2];                                      \
            _Pragma("unroll")                                                 \
            for (int nt = 0; nt < 4; nt++) {                                  \
                const int rn = n_base + nt * 8 + gid;                         \
                bH[nt][0] = *(const uint32_t*)(Bhi + rn * SPITCH + k0);       \
                bH[nt][1] = *(const uint32_t*)(Bhi + rn * SPITCH + k0 + 8);   \
                bL[nt][0] = *(const uint32_t*)(Blo + rn * SPITCH + k0);       \
                bL[nt][1] = *(const uint32_t*)(Blo + rn * SPITCH + k0 + 8);   \
            }                                                                 \
            _Pragma("unroll")                                                 \
            for (int t = 0; t < 4; t++) {                                     \
                const int r = m_base + t * 16 + gid;                          \
                uint32_t aH[4], aL[4];                                        \
                aH[0] = *(const uint32_t*)(Ahi + r * SPITCH + k0);            \
                aH[1] = *(const uint32_t*)(Ahi + (r + 8) * SPITCH + k0);      \
                aH[2] = *(const uint32_t*)(Ahi + r * SPITCH + k0 + 8);        \
                aH[3] = *(const uint32_t*)(Ahi + (r + 8) * SPITCH + k0 + 8);  \
                aL[0] = *(const uint32_t*)(Alo + r * SPITCH + k0);            \
                aL[1] = *(const uint32_t*)(Alo + (r + 8) * SPITCH + k0);      \
                aL[2] = *(const uint32_t*)(Alo + r * SPITCH + k0 + 8);        \
                aL[3] = *(const uint32_t*)(Alo + (r + 8) * SPITCH + k0 + 8);  \
                _Pragma("unroll")                                             \
                for (int nt = 0; nt < 4; nt++)                                \
                    MMA16816(acc[t][nt], aH[0], aH[1], aH[2], aH[3],          \
                             bH[nt][0], bH[nt][1]);                           \
                _Pragma("unroll")                                             \
                for (int nt = 0; nt < 4; nt++)                                \
                    MMA16816(acc[t][nt], aH[0], aH[1], aH[2], aH[3],          \
                             bL[nt][0], bL[nt][1]);                           \
                _Pragma("unroll")                                             \
                for (int nt = 0; nt < 4; nt++)                                \
                    MMA16816(acc[t][nt], aL[0], aL[1], aL[2], aL[3],          \
                             bH[nt][0], bH[nt][1]);                           \
            }                                                                 \
        }                                                                     \
        if (it + 1 < 16) {                                                    \
            STORE_A_IMPL(cur ^ 1);                                            \
            asm volatile("cp.async.wait_group 0;" ::: "memory");              \
        }                                                                     \
        __syncthreads();                                                      \
    }

template <bool IS_G>
__global__ __launch_bounds__(256, 2)
void gemm_half(const float* __restrict__ x, const int* __restrict__ ix,
               const float* __restrict__ bias) {
    extern __shared__ __nv_bfloat16 sm[];

    const int tid  = threadIdx.x;
    const int l    = tid & 31;
    const int warp = tid >> 5;
    const int bx   = blockIdx.x;          // 0..3 -> 128-col stripe of this half
    const int row0 = blockIdx.y * 128;
    const int n0g  = (IS_G ? 512 : 0) + bx * 128;

    const int wm = warp >> 2;
    const int wn = warp & 3;
    const int m_base = wm * 64;
    const int n_base = wn * 32;
    const int gid = l >> 2, tig = l & 3;

    float acc[4][4][4];
#pragma unroll
    for (int t = 0; t < 4; t++)
#pragma unroll
        for (int n = 0; n < 4; n++)
#pragma unroll
            for (int r = 0; r < 4; r++) acc[t][n][r] = 0.f;

    float4 stg[4];

    MAINLOOP_BODY(x, g_whi, g_wlo, C_DIM)

    // ---- epilogue (R11 exact) ----
#pragma unroll
    for (int t = 0; t < 4; t++) {
#pragma unroll
        for (int h = 0; h < 2; h++) {
            const int m = row0 + m_base + t * 16 + gid + h * 8;
            const int grp = ix[m];
#pragma unroll
            for (int nt = 0; nt < 4; nt++) {
                const int cg = n0g + n_base + nt * 8 + 2 * tig;
                const int cw = cg & 511;
                float v0 = acc[t][nt][2 * h]     + bias[cw];
                float v1 = acc[t][nt][2 * h + 1] + bias[cw + 1];
                if (IS_G) {
                    v0 = __expf(v0);
                    v1 = __expf(v1);
                    __half2 eq = __floats2half2_rn(v0, v1);
                    *(__half2*)&g_eg[(size_t)m * C_DIM + cw] = eq;
                    float q0 = __half2float(__low2half(eq));
                    float q1 = __half2float(__high2half(eq));
                    float* dp = &g_denom[(size_t)grp * C_DIM + cw];
                    atomicAdd(dp,     q0);
                    atomicAdd(dp + 1, q1);
                } else {
                    __half2 eh = *(const __half2*)&g_eg[(size_t)m * C_DIM + cw];
                    float2 e = __half22float2(eh);
                    float2 d = *(const float2*)&g_denom[(size_t)grp * C_DIM + cw]; // reciprocal
                    float* yp = &g_y[(size_t)grp * C_DIM + cw];
                    atomicAdd(yp,     v0 * e.x * d.x);
                    atomicAdd(yp + 1, v1 * e.y * d.y);
                }
            }
        }
    }
}

// ---------------- yh = y @ Wh + bh via bf16-split mma (same mainloop) ----------
__global__ __launch_bounds__(256, 2)
void gemm_h_mma(const float* __restrict__ bh) {
    extern __shared__ __nv_bfloat16 sm[];

    const int tid  = threadIdx.x;
    const int l    = tid & 31;
    const int warp = tid >> 5;
    const int bx   = blockIdx.x;          // 0..3 -> 128-col stripe of 512
    const int row0 = blockIdx.y * 128;    // 0..31 row blocks of G_DIM
    const int n0g  = bx * 128;

    const int wm = warp >> 2;
    const int wn = warp & 3;
    const int m_base = wm * 64;
    const int n_base = wn * 32;
    const int gid = l >> 2, tig = l & 3;

    float acc[4][4][4];
#pragma unroll
    for (int t = 0; t < 4; t++)
#pragma unroll
        for (int n = 0; n < 4; n++)
#pragma unroll
            for (int r = 0; r < 4; r++) acc[t][n][r] = 0.f;

    float4 stg[4];

    MAINLOOP_BODY(g_y, g_whh, g_wlh, C_DIM)

    // ---- epilogue: bias + store ----
#pragma unroll
    for (int t = 0; t < 4; t++) {
#pragma unroll
        for (int h = 0; h < 2; h++) {
            const int m = row0 + m_base + t * 16 + gid + h * 8;
#pragma unroll
            for (int nt = 0; nt < 4; nt++) {
                const int cw = n0g + n_base + nt * 8 + 2 * tig;
                float v0 = acc[t][nt][2 * h]     + bh[cw];
                float v1 = acc[t][nt][2 * h + 1] + bh[cw + 1];
                *(float2*)&g_yh[(size_t)m * C_DIM + cw] = make_float2(v0, v1);
            }
        }
    }
}

// ---------------- out[n] = yh[ix[n]] ----------------
__global__ void gather_kernel(const int* __restrict__ ix, float* __restrict__ out) {
    size_t idx = (size_t)blockIdx.x * blockDim.x + threadIdx.x;  // N*C/4
    int n  = (int)(idx >> 7);
    int cq = (int)(idx & 127) << 2;
    int g  = ix[n];
    *(float4*)&out[((size_t)n << 9) + cq] = *(const float4*)&g_yh[((size_t)g << 9) + cq];
}

extern "C" void kernel_launch(void* const* d_in, const int* in_sizes, int n_in,
                              void* d_out, int out_size) {
    const float* x  = (const float*)d_in[0];
    const int*   ix = (const int*)d_in[1];
    const float* Wf = (const float*)d_in[2];
    const float* bf = (const float*)d_in[3];
    const float* Wg = (const float*)d_in[4];
    const float* bg = (const float*)d_in[5];
    const float* Wh = (const float*)d_in[6];
    const float* bh = (const float*)d_in[7];
    float* out = (float*)d_out;

    const int SMEM = 2 * 4 * TILE_E * 2;   // 81920 bytes
    cudaFuncSetAttribute(gemm_half<true>,  cudaFuncAttributeMaxDynamicSharedMemorySize, SMEM);
    cudaFuncSetAttribute(gemm_half<false>, cudaFuncAttributeMaxDynamicSharedMemorySize, SMEM);
    cudaFuncSetAttribute(gemm_h_mma,       cudaFuncAttributeMaxDynamicSharedMemorySize, SMEM);

    zero_kernel<<<(G_DIM * C_DIM / 4) / 256, 256>>>();
    build_w_kernel<<<(NOUT * C_DIM) / 256, 256>>>(Wf, Wg);
    build_wh_kernel<<<(C_DIM * C_DIM) / 256, 256>>>(Wh);

    dim3 g1(4, N_ELEM / 128);
    gemm_half<true><<<g1, 256, SMEM>>>(x, ix, bg);    // eg(fp16) + denom
    rcp_kernel<<<(G_DIM * C_DIM / 4) / 256, 256>>>(); // denom -> 1/denom
    gemm_half<false><<<g1, 256, SMEM>>>(x, ix, bf);   // fx, fused aggregation

    dim3 g2(4, G_DIM / 128);
    gemm_h_mma<<<g2, 256, SMEM>>>(bh);

    gather_kernel<<<(N_ELEM * (C_DIM / 4)) / 256, 256>>>(ix, out);
}

// round 14
// speedup vs baseline: 1.7209x; 1.0326x over previous
#include <cuda_runtime.h>
#include <cuda_bf16.h>
#include <cuda_fp16.h>
#include <math.h>
#include <stdint.h>

#define N_ELEM 131072
#define C_DIM  512
#define G_DIM  4096
#define NOUT   1024     // Wf cols || Wg cols

// ---------------- scratch (device globals; no allocation allowed) ----------------
__device__ __nv_bfloat16 g_whi[(size_t)NOUT * C_DIM];     // 1 MB, K-major [n][k]
__device__ __nv_bfloat16 g_wlo[(size_t)NOUT * C_DIM];     // 1 MB
__device__ __nv_bfloat16 g_whh[(size_t)C_DIM * C_DIM];    // 0.5 MB, Wh hi, K-major
__device__ __nv_bfloat16 g_wlh[(size_t)C_DIM * C_DIM];    // 0.5 MB, Wh lo
__device__ __half g_eg[(size_t)N_ELEM * C_DIM];           // 128 MB (fp16)
__device__ float g_denom[G_DIM * C_DIM];                  // 8 MB (then reciprocal)
__device__ float g_y[G_DIM * C_DIM];                      // 8 MB
__device__ float g_yh[G_DIM * C_DIM];                     // 8 MB

#define MMA16816(d, a0, a1, a2, a3, b0, b1) \
    asm volatile("mma.sync.aligned.m16n8k16.row.col.f32.bf16.bf16.f32 " \
                 "{%0,%1,%2,%3}, {%4,%5,%6,%7}, {%8,%9}, {%0,%1,%2,%3};" \
                 : "+f"((d)[0]), "+f"((d)[1]), "+f"((d)[2]), "+f"((d)[3]) \
                 : "r"(a0), "r"(a1), "r"(a2), "r"(a3), "r"(b0), "r"(b1))

__device__ __forceinline__ uint32_t smem_u32(const void* p) {
    uint32_t a;
    asm("{ .reg .u64 t; cvta.to.shared.u64 t, %1; cvt.u32.u64 %0, t; }" : "=r"(a) : "l"(p));
    return a;
}
__device__ __forceinline__ void cp16(uint32_t saddr, const void* g) {
    asm volatile("cp.async.cg.shared.global [%0], [%1], 16;" :: "r"(saddr), "l"(g));
}

// ---------------- zero accumulators ----------------
__global__ void zero_kernel() {
    int i = blockIdx.x * blockDim.x + threadIdx.x;   // G*C/4
    float4 z = make_float4(0.f, 0.f, 0.f, 0.f);
    ((float4*)g_denom)[i] = z;
    ((float4*)g_y)[i] = z;
}

// ---------------- denom -> 1/denom (between the two gemm halves) ----------------
__global__ void rcp_kernel() {
    int i = blockIdx.x * blockDim.x + threadIdx.x;   // G*C/4
    float4 d = ((float4*)g_denom)[i];
    d.x = 1.0f / d.x;
    d.y = 1.0f / d.y;
    d.z = 1.0f / d.z;
    d.w = 1.0f / d.w;
    ((float4*)g_denom)[i] = d;
}

// ---------------- build Whi/Wlo [n=1024][k=512] K-major bf16 ----------------
__global__ void build_w_kernel(const float* __restrict__ Wf,
                               const float* __restrict__ Wg) {
    int i = blockIdx.x * blockDim.x + threadIdx.x;   // NOUT*C_DIM
    int n = i >> 9;
    int k = i & 511;
    const float* W = (n < 512) ? Wf : Wg;
    float w = W[(size_t)k * C_DIM + (n & 511)];
    __nv_bfloat16 hi = __float2bfloat16(w);
    g_whi[i] = hi;
    g_wlo[i] = __float2bfloat16(w - __bfloat162float(hi));
}

// ---------------- build Wh hi/lo [n=512][k=512] K-major bf16 ----------------
__global__ void build_wh_kernel(const float* __restrict__ Wh) {
    int i = blockIdx.x * blockDim.x + threadIdx.x;   // C_DIM*C_DIM
    int n = i >> 9;
    int k = i & 511;
    float w = Wh[(size_t)k * C_DIM + n];
    __nv_bfloat16 hi = __float2bfloat16(w);
    g_whh[i] = hi;
    g_wlh[i] = __float2bfloat16(w - __bfloat162float(hi));
}

// ---------------- mma.sync bf16-split GEMM halves ------------------------------
// A stored in FRAGMENT-CONTIGUOUS smem layout: 16 blocks (tile16 x kstep), each
// 32 granules x 16B (+16B pad -> block stride 528B shifts banks by 4). Granule l
// holds lane-l's fragment quad [ (r,k0), (r+8,k0), (r,k0+8), (r+8,k0+8) ].
// Reader: 1 conflict-free LDS.128 per (t, hi/lo) per kstep (was 8 LDS.32).
// Writer: 16 STS.32 at precomputed offsets (<=2-way conflicts).
// B path, MMA order, LDG A-source (L1 locality), epilogues: identical to R13.
#define SPITCH 40                       // B pitch in bf16 elems (80B)
#define A_TILE_BYTES 8448               // 16 blocks * 528B
#define B_TILE_BYTES 10240              // 128 rows * 80B
#define STG_BYTES (2 * A_TILE_BYTES + 2 * B_TILE_BYTES)   // 37376
#define B_OFF (2 * A_TILE_BYTES)        // BHI offset within stage

#define PRECOMP_A_OFFS()                                                      \
    uint32_t aoff[4][2];                                                      \
    _Pragma("unroll")                                                         \
    for (int i_ = 0; i_ < 4; i_++) {                                          \
        int u_ = tid + 256 * i_;                                              \
        int r_ = u_ >> 3, sq_ = u_ & 7;                                       \
        _Pragma("unroll")                                                     \
        for (int q_ = 0; q_ < 2; q_++) {                                      \
            int w_ = 2 * sq_ + q_;                                            \
            int s_ = w_ >> 3, rem_ = w_ & 7;                                  \
            int tg_ = rem_ & 3, kk_ = rem_ >> 2;                              \
            aoff[i_][q_] = (uint32_t)(((r_ >> 4) * 2 + s_) * 528 +            \
                                      ((r_ & 7) * 4 + tg_) * 16 +             \
                                      kk_ * 8 + ((r_ >> 3) & 1) * 4);         \
        }                                                                     \
    }

#define LOAD_A_IMPL(SRC, CH) do {                                             \
        const int kc_ = (CH) * 32;                                            \
        _Pragma("unroll")                                                     \
        for (int i_ = 0; i_ < 4; i_++) {                                      \
            int u_ = tid + i_ * 256;                                          \
            int r_ = u_ >> 3, s_ = u_ & 7;                                    \
            stg[i_] = *(const float4*)((SRC) + (size_t)(row0 + r_) * C_DIM + kc_ + s_ * 4); \
        }                                                                     \
    } while (0)

#define STORE_A_IMPL(BUF) do {                                                \
        char* ahi_ = (char*)sm + (BUF) * STG_BYTES;                           \
        char* alo_ = ahi_ + A_TILE_BYTES;                                     \
        _Pragma("unroll")                                                     \
        for (int i_ = 0; i_ < 4; i_++) {                                      \
            float4 v_ = stg[i_];                                              \
            __nv_bfloat162 h01_, h23_, l01_, l23_;                            \
            h01_.x = __float2bfloat16(v_.x); h01_.y = __float2bfloat16(v_.y); \
            h23_.x = __float2bfloat16(v_.z); h23_.y = __float2bfloat16(v_.w); \
            l01_.x = __float2bfloat16(v_.x - __bfloat162float(h01_.x));       \
            l01_.y = __float2bfloat16(v_.y - __bfloat162float(h01_.y));       \
            l23_.x = __float2bfloat16(v_.z - __bfloat162float(h23_.x));       \
            l23_.y = __float2bfloat16(v_.w - __bfloat162float(h23_.y));       \
            *(uint32_t*)(ahi_ + aoff[i_][0]) = *(uint32_t*)&h01_;             \
            *(uint32_t*)(ahi_ + aoff[i_][1]) = *(uint32_t*)&h23_;             \
            *(uint32_t*)(alo_ + aoff[i_][0]) = *(uint32_t*)&l01_;             \
            *(uint32_t*)(alo_ + aoff[i_][1]) = *(uint32_t*)&l23_;             \
        }                                                                     \
    } while (0)

#define LOAD_B_IMPL(WH, WL, KSTRIDE, BUF, CH) do {                            \
        const int kc_ = (CH) * 32;                                            \
        uint32_t bhi_ = smem_u32((char*)sm + (BUF) * STG_BYTES + B_OFF);      \
        uint32_t blo_ = bhi_ + B_TILE_BYTES;                                  \
        _Pragma("unroll")                                                     \
        for (int i_ = 0; i_ < 2; i_++) {                                      \
            int u_ = tid + i_ * 256;                                          \
            int nr_ = u_ >> 2, ch_ = u_ & 3;                                  \
            size_t go_ = (size_t)(n0g + nr_) * (KSTRIDE) + kc_ + ch_ * 8;     \
            uint32_t so_ = nr_ * (SPITCH * 2) + ch_ * 16;                     \
            cp16(bhi_ + so_, (WH) + go_);                                     \
            cp16(blo_ + so_, (WL) + go_);                                     \
        }                                                                     \
        asm volatile("cp.async.commit_group;" ::: "memory");                  \
    } while (0)

#define MAINLOOP_BODY(ASRC, WH, WL, KSTRIDE)                                  \
    LOAD_B_IMPL(WH, WL, KSTRIDE, 0, 0);                                       \
    LOAD_A_IMPL(ASRC, 0);                                                     \
    STORE_A_IMPL(0);                                                          \
    asm volatile("cp.async.wait_group 0;" ::: "memory");                      \
    __syncthreads();                                                          \
    for (int it = 0; it < 16; it++) {                                         \
        const int cur = it & 1;                                               \
        if (it + 1 < 16) {                                                    \
            LOAD_B_IMPL(WH, WL, KSTRIDE, cur ^ 1, it + 1);                    \
            LOAD_A_IMPL(ASRC, it + 1);                                        \
        }                                                                     \
        const char* Ab = (const char*)sm + cur * STG_BYTES;                   \
        const __nv_bfloat16* Bhi = (const __nv_bfloat16*)(Ab + B_OFF);        \
        const __nv_bfloat16* Blo = (const __nv_bfloat16*)(Ab + B_OFF + B_TILE_BYTES); \
        _Pragma("unroll")                                                     \
        for (int s = 0; s < 2; s++) {                                         \
            const int k0 = s * 16 + 2 * tig;                                  \
            uint32_t bH[4][2], bL[4][2];                                      \
            _Pragma("unroll")                                                 \
            for (int nt = 0; nt < 4; nt++) {                                  \
                const int rn = n_base + nt * 8 + gid;                         \
                bH[nt][0] = *(const uint32_t*)(Bhi + rn * SPITCH + k0);       \
                bH[nt][1] = *(const uint32_t*)(Bhi + rn * SPITCH + k0 + 8);   \
                bL[nt][0] = *(const uint32_t*)(Blo + rn * SPITCH + k0);       \
                bL[nt][1] = *(const uint32_t*)(Blo + rn * SPITCH + k0 + 8);   \
            }                                                                 \
            _Pragma("unroll")                                                 \
            for (int t = 0; t < 4; t++) {                                     \
                const uint32_t ar = (uint32_t)((((wm * 4 + t) * 2 + s) * 528) + l * 16); \
                uint4 qh = *(const uint4*)(Ab + ar);                          \
                uint4 ql = *(const uint4*)(Ab + A_TILE_BYTES + ar);           \
                _Pragma("unroll")                                             \
                for (int nt = 0; nt < 4; nt++)                                \
                    MMA16816(acc[t][nt], qh.x, qh.y, qh.z, qh.w,              \
                             bH[nt][0], bH[nt][1]);                           \
                _Pragma("unroll")                                             \
                for (int nt = 0; nt < 4; nt++)                                \
                    MMA16816(acc[t][nt], qh.x, qh.y, qh.z, qh.w,              \
                             bL[nt][0], bL[nt][1]);                           \
                _Pragma("unroll")                                             \
                for (int nt = 0; nt < 4; nt++)                                \
                    MMA16816(acc[t][nt], ql.x, ql.y, ql.z, ql.w,              \
                             bH[nt][0], bH[nt][1]);                           \
            }                                                                 \
        }                                                                     \
        if (it + 1 < 16) {                                                    \
            STORE_A_IMPL(cur ^ 1);                                            \
            asm volatile("cp.async.wait_group 0;" ::: "memory");              \
        }                                                                     \
        __syncthreads();                                                      \
    }

template <bool IS_G>
__global__ __launch_bounds__(256, 2)
void gemm_half(const float* __restrict__ x, const int* __restrict__ ix,
               const float* __restrict__ bias) {
    extern __shared__ __nv_bfloat16 sm[];

    const int tid  = threadIdx.x;
    const int l    = tid & 31;
    const int warp = tid >> 5;
    const int bx   = blockIdx.x;          // 0..3 -> 128-col stripe of this half
    const int row0 = blockIdx.y * 128;
    const int n0g  = (IS_G ? 512 : 0) + bx * 128;

    const int wm = warp >> 2;
    const int wn = warp & 3;
    const int m_base = wm * 64;
    const int n_base = wn * 32;
    const int gid = l >> 2, tig = l & 3;

    float acc[4][4][4];
#pragma unroll
    for (int t = 0; t < 4; t++)
#pragma unroll
        for (int n = 0; n < 4; n++)
#pragma unroll
            for (int r = 0; r < 4; r++) acc[t][n][r] = 0.f;

    float4 stg[4];
    PRECOMP_A_OFFS()

    MAINLOOP_BODY(x, g_whi, g_wlo, C_DIM)

    // ---- epilogue (R13 exact) ----
#pragma unroll
    for (int t = 0; t < 4; t++) {
#pragma unroll
        for (int h = 0; h < 2; h++) {
            const int m = row0 + m_base + t * 16 + gid + h * 8;
            const int grp = ix[m];
#pragma unroll
            for (int nt = 0; nt < 4; nt++) {
                const int cg = n0g + n_base + nt * 8 + 2 * tig;
                const int cw = cg & 511;
                float v0 = acc[t][nt][2 * h]     + bias[cw];
                float v1 = acc[t][nt][2 * h + 1] + bias[cw + 1];
                if (IS_G) {
                    v0 = __expf(v0);
                    v1 = __expf(v1);
                    __half2 eq = __floats2half2_rn(v0, v1);
                    *(__half2*)&g_eg[(size_t)m * C_DIM + cw] = eq;
                    float q0 = __half2float(__low2half(eq));
                    float q1 = __half2float(__high2half(eq));
                    float* dp = &g_denom[(size_t)grp * C_DIM + cw];
                    atomicAdd(dp,     q0);
                    atomicAdd(dp + 1, q1);
                } else {
                    __half2 eh = *(const __half2*)&g_eg[(size_t)m * C_DIM + cw];
                    float2 e = __half22float2(eh);
                    float2 d = *(const float2*)&g_denom[(size_t)grp * C_DIM + cw]; // reciprocal
                    float* yp = &g_y[(size_t)grp * C_DIM + cw];
                    atomicAdd(yp,     v0 * e.x * d.x);
                    atomicAdd(yp + 1, v1 * e.y * d.y);
                }
            }
        }
    }
}

// ---------------- yh = y @ Wh + bh via bf16-split mma (same mainloop) ----------
__global__ __launch_bounds__(256, 2)
void gemm_h_mma(const float* __restrict__ bh) {
    extern __shared__ __nv_bfloat16 sm[];

    const int tid  = threadIdx.x;
    const int l    = tid & 31;
    const int warp = tid >> 5;
    const int bx   = blockIdx.x;          // 0..3 -> 128-col stripe of 512
    const int row0 = blockIdx.y * 128;    // 0..31 row blocks of G_DIM
    const int n0g  = bx * 128;

    const int wm = warp >> 2;
    const int wn = warp & 3;
    const int m_base = wm * 64;
    const int n_base = wn * 32;
    const int gid = l >> 2, tig = l & 3;

    float acc[4][4][4];
#pragma unroll
    for (int t = 0; t < 4; t++)
#pragma unroll
        for (int n = 0; n < 4; n++)
#pragma unroll
            for (int r = 0; r < 4; r++) acc[t][n][r] = 0.f;

    float4 stg[4];
    PRECOMP_A_OFFS()

    MAINLOOP_BODY(g_y, g_whh, g_wlh, C_DIM)

    // ---- epilogue: bias + store ----
#pragma unroll
    for (int t = 0; t < 4; t++) {
#pragma unroll
        for (int h = 0; h < 2; h++) {
            const int m = row0 + m_base + t * 16 + gid + h * 8;
#pragma unroll
            for (int nt = 0; nt < 4; nt++) {
                const int cw = n0g + n_base + nt * 8 + 2 * tig;
                float v0 = acc[t][nt][2 * h]     + bh[cw];
                float v1 = acc[t][nt][2 * h + 1] + bh[cw + 1];
                *(float2*)&g_yh[(size_t)m * C_DIM + cw] = make_float2(v0, v1);
            }
        }
    }
}

// ---------------- out[n] = yh[ix[n]] ----------------
__global__ void gather_kernel(const int* __restrict__ ix, float* __restrict__ out) {
    size_t idx = (size_t)blockIdx.x * blockDim.x + threadIdx.x;  // N*C/4
    int n  = (int)(idx >> 7);
    int cq = (int)(idx & 127) << 2;
    int g  = ix[n];
    *(float4*)&out[((size_t)n << 9) + cq] = *(const float4*)&g_yh[((size_t)g << 9) + cq];
}

extern "C" void kernel_launch(void* const* d_in, const int* in_sizes, int n_in,
                              void* d_out, int out_size) {
    const float* x  = (const float*)d_in[0];
    const int*   ix = (const int*)d_in[1];
    const float* Wf = (const float*)d_in[2];
    const float* bf = (const float*)d_in[3];
    const float* Wg = (const float*)d_in[4];
    const float* bg = (const float*)d_in[5];
    const float* Wh = (const float*)d_in[6];
    const float* bh = (const float*)d_in[7];
    float* out = (float*)d_out;

    const int SMEM = 2 * STG_BYTES;   // 74752 bytes
    cudaFuncSetAttribute(gemm_half<true>,  cudaFuncAttributeMaxDynamicSharedMemorySize, SMEM);
    cudaFuncSetAttribute(gemm_half<false>, cudaFuncAttributeMaxDynamicSharedMemorySize, SMEM);
    cudaFuncSetAttribute(gemm_h_mma,       cudaFuncAttributeMaxDynamicSharedMemorySize, SMEM);

    zero_kernel<<<(G_DIM * C_DIM / 4) / 256, 256>>>();
    build_w_kernel<<<(NOUT * C_DIM) / 256, 256>>>(Wf, Wg);
    build_wh_kernel<<<(C_DIM * C_DIM) / 256, 256>>>(Wh);

    dim3 g1(4, N_ELEM / 128);
    gemm_half<true><<<g1, 256, SMEM>>>(x, ix, bg);    // eg(fp16) + denom
    rcp_kernel<<<(G_DIM * C_DIM / 4) / 256, 256>>>(); // denom -> 1/denom
    gemm_half<false><<<g1, 256, SMEM>>>(x, ix, bf);   // fx, fused aggregation

    dim3 g2(4, G_DIM / 128);
    gemm_h_mma<<<g2, 256, SMEM>>>(bh);

    gather_kernel<<<(N_ELEM * (C_DIM / 4)) / 256, 256>>>(ix, out);
}